// round 11
// baseline (speedup 1.0000x reference)
#include <cuda_runtime.h>

#define NODES 7
#define CH 256
#define HID 128
#define P_TOTAL 65536
#define PLANE64 32768           // u64 elements per channel plane
#define PF 4                    // prefetch depth (channels)
#define GEMM_BLKS 14
#define STREAM_BLKS 256

typedef unsigned long long ull;

__device__ float g_nw[2 * NODES * CH];   // new_weight [b, n, c]
__device__ int   g_done = 0;             // GEMM blocks completed
__device__ int   g_fin  = 0;             // stream blocks completed

// ---------------------------------------------------------------------------
__device__ __forceinline__ ull fma2(ull a, ull b, ull c) {
    ull d;
    asm("fma.rn.f32x2 %0, %1, %2, %3;" : "=l"(d) : "l"(a), "l"(b), "l"(c));
    return d;
}
__device__ __forceinline__ ull add2(ull a, ull b) {
    ull d;
    asm("add.rn.f32x2 %0, %1, %2;" : "=l"(d) : "l"(a), "l"(b));
    return d;
}
__device__ __forceinline__ ull pack2(float x, float y) {
    ull r;
    asm("mov.b64 %0, {%1, %2};" : "=l"(r) : "f"(x), "f"(y));
    return r;
}
__device__ __forceinline__ void unpack2(ull v, float& x, float& y) {
    asm("mov.b64 {%0, %1}, %2;" : "=f"(x), "=f"(y) : "l"(v));
}
__device__ __forceinline__ ull ldcs64(const ull* p) {
    ull v;
    asm volatile("ld.global.cs.b64 %0, [%1];" : "=l"(v) : "l"(p));
    return v;
}
__device__ __forceinline__ void stcs64(ull* p, ull v) {
    asm volatile("st.global.cs.b64 [%0], %1;" :: "l"(p), "l"(v));
}

// ---------------------------------------------------------------------------
// Single launch, 512-thread blocks.
//   Blocks 0..13   : new_weight GEMM (bn = bid), signal g_done.
//   Blocks 14..269 : stream. Each covers 512 consecutive points (2KB/plane).
//     half = tid>>8 owns channels [128*half, 128*half+128).
//     Each thread: one u64 lane = 2 points; 128 LDG.64 in, 128 STG.64 out.
// ---------------------------------------------------------------------------
__global__ void __launch_bounds__(512, 2) fused_kernel(
    const float* __restrict__ inp,     // [1,2,7,128]
    const float* __restrict__ res,     // [2, 256, 65536]
    const float* __restrict__ Wres,    // [256, 7]
    const float* __restrict__ nfh,     // [128,1]
    const float* __restrict__ weight,  // [128, 256]
    float* __restrict__ out)           // [2, 256, 65536]
{
    const int tid = threadIdx.x;
    const int bid = blockIdx.x;

    // ================= GEMM blocks =================
    if (bid < GEMM_BLKS) {
        if (tid < CH) {
            const int bn = bid;          // 0..13 = b*7+n
            float acc = 0.f;
#pragma unroll 16
            for (int h = 0; h < HID; ++h)
                acc += __ldg(inp + bn * HID + h) * weight[h * CH + tid];
            g_nw[bn * CH + tid] = acc;
        }
        __syncthreads();
        __threadfence();
        if (tid == 0) atomicAdd(&g_done, 1);
        return;
    }

    // ================= stream blocks =================
    __shared__ ull Wd[CH][8];            // (w[c][n], w[c][n]) duplicated
    __shared__ ull NWd[CH][8];           // (nw[n][c], nw[n][c]) duplicated
    __shared__ ull part[NODES][2][256];  // packed per-half point-pair partials
    __shared__ float sh_n2[8];

    const int sb   = bid - GEMM_BLKS;    // 0..255
    const int b    = sb >> 7;            // 0..1
    const int tile = sb & 127;           // 0..127 (512 points each)
    const int half = tid >> 8;           // channel half
    const int pl   = tid & 255;          // u64 lane within block
    const int wid  = tid >> 5;
    const int lane = tid & 31;

    // n2[b][n]: warps 0..6 compute the 128-dot via shuffle
    if (wid < NODES) {
        float s = 0.f;
#pragma unroll
        for (int i = 0; i < 4; ++i) {
            int h = lane + 32 * i;
            s += __ldg(inp + b * NODES * HID + wid * HID + h) * __ldg(nfh + h);
        }
#pragma unroll
        for (int o = 16; o; o >>= 1)
            s += __shfl_xor_sync(0xffffffffu, s, o);
        if (lane == 0) sh_n2[wid] = s;
    }
    // Duplicated Wres staging: thread c (<256) handles channel c
    if (tid < CH) {
#pragma unroll
        for (int n = 0; n < NODES; ++n) {
            float w = Wres[tid * NODES + n];
            Wd[tid][n] = pack2(w, w);
        }
        Wd[tid][7] = 0ull;
    }
    __syncthreads();

    float n2s[NODES];
#pragma unroll
    for (int n = 0; n < NODES; ++n) n2s[n] = sh_n2[n];

    const int cbase = half * 128;
    const ull* rf = (const ull*)res + (size_t)b * CH * PLANE64
                    + (size_t)cbase * PLANE64 + (size_t)tile * 256 + pl;

    ull acc[NODES];
#pragma unroll
    for (int n = 0; n < NODES; ++n) acc[n] = 0ull;

    // ---- Pass 1: partial n1 over this half's 128 channels (LDG.64/channel)
    ull buf[PF];
#pragma unroll
    for (int i = 0; i < PF; ++i)
        buf[i] = ldcs64(rf + (size_t)i * PLANE64);

#pragma unroll 1
    for (int cb = 0; cb < 128; cb += PF) {
#pragma unroll
        for (int i = 0; i < PF; ++i) {
            ull v = buf[i];
            if (cb + PF < 128)
                buf[i] = ldcs64(rf + (size_t)(cb + PF + i) * PLANE64);
            const ulonglong2* wr = (const ulonglong2*)(&Wd[cbase + cb + i][0]);
            ulonglong2 w01 = wr[0];
            ulonglong2 w23 = wr[1];
            ulonglong2 w45 = wr[2];
            ulonglong2 w6p = wr[3];
            acc[0] = fma2(v, w01.x, acc[0]);
            acc[1] = fma2(v, w01.y, acc[1]);
            acc[2] = fma2(v, w23.x, acc[2]);
            acc[3] = fma2(v, w23.y, acc[3]);
            acc[4] = fma2(v, w45.x, acc[4]);
            acc[5] = fma2(v, w45.y, acc[5]);
            acc[6] = fma2(v, w6p.x, acc[6]);
        }
    }

    // ---- Exchange packed partials between the two channel halves
#pragma unroll
    for (int n = 0; n < NODES; ++n)
        part[n][half][pl] = acc[n];
    __syncthreads();

    float s0[NODES], s1[NODES];
#pragma unroll
    for (int n = 0; n < NODES; ++n) {
        ull tot = add2(acc[n], part[n][half ^ 1][pl]);
        float x, y;
        unpack2(tot, x, y);
        s0[n] = x + n2s[n];
        s1[n] = y + n2s[n];
    }

    // ---- Softmax over 7 nodes, both points
    float m0 = s0[0], m1 = s1[0];
#pragma unroll
    for (int n = 1; n < NODES; ++n) { m0 = fmaxf(m0, s0[n]); m1 = fmaxf(m1, s1[n]); }
    float t0 = 0.f, t1 = 0.f;
    float e0[NODES], e1[NODES];
#pragma unroll
    for (int n = 0; n < NODES; ++n) {
        e0[n] = __expf(s0[n] - m0); t0 += e0[n];
        e1[n] = __expf(s1[n] - m1); t1 += e1[n];
    }
    float i0 = __fdividef(1.f, t0);
    float i1 = __fdividef(1.f, t1);
    ull attn2[NODES];
#pragma unroll
    for (int n = 0; n < NODES; ++n)
        attn2[n] = pack2(e0[n] * i0, e1[n] * i1);

    // ---- Wait for GEMM blocks (expected zero spin), stage NWd
    if (tid == 0) {
        while (*(volatile int*)&g_done < GEMM_BLKS) { }
    }
    __syncthreads();
    __threadfence();
    if (tid < CH) {
#pragma unroll
        for (int n = 0; n < NODES; ++n) {
            float q = g_nw[(b * NODES + n) * CH + tid];
            NWd[tid][n] = pack2(q, q);
        }
        NWd[tid][7] = 0ull;
    }
    __syncthreads();

    // ---- Pass 2: this half's 128 channels, STG.64 covers both points
    ull* op = (ull*)out + (size_t)b * CH * PLANE64
              + (size_t)cbase * PLANE64 + (size_t)tile * 256 + pl;
#pragma unroll 4
    for (int c = 0; c < 128; ++c) {
        const ulonglong2* nr = (const ulonglong2*)(&NWd[cbase + c][0]);
        ulonglong2 q01 = nr[0];
        ulonglong2 q23 = nr[1];
        ulonglong2 q45 = nr[2];
        ulonglong2 q6p = nr[3];
        ull o = 0ull;
        o = fma2(attn2[0], q01.x, o);
        o = fma2(attn2[1], q01.y, o);
        o = fma2(attn2[2], q23.x, o);
        o = fma2(attn2[3], q23.y, o);
        o = fma2(attn2[4], q45.x, o);
        o = fma2(attn2[5], q45.y, o);
        o = fma2(attn2[6], q6p.x, o);
        float v0, v1;
        unpack2(o, v0, v1);
        stcs64(op + (size_t)c * PLANE64, pack2(fmaxf(v0, 0.f), fmaxf(v1, 0.f)));
    }

    // ---- Completion accounting; last stream block resets counters
    __syncthreads();
    if (tid == 0) {
        __threadfence();
        int v = atomicAdd(&g_fin, 1);
        if (v == STREAM_BLKS - 1) {
            atomicExch(&g_done, 0);
            atomicExch(&g_fin, 0);
        }
    }
}

// ---------------------------------------------------------------------------
extern "C" void kernel_launch(void* const* d_in, const int* in_sizes, int n_in,
                              void* d_out, int out_size) {
    const float* inp    = (const float*)d_in[0];  // [1,2,7,128]
    const float* res    = (const float*)d_in[1];  // [2,256,16,64,64]
    const float* Wres   = (const float*)d_in[2];  // [256,7]
    const float* nfh    = (const float*)d_in[3];  // [128,1]
    const float* weight = (const float*)d_in[4];  // [128,256]

    fused_kernel<<<GEMM_BLKS + STREAM_BLKS, 512>>>(inp, res, Wres, nfh, weight,
                                                   (float*)d_out);
}

// round 12
// speedup vs baseline: 1.0684x; 1.0684x over previous
#include <cuda_runtime.h>
#include <cstdint>

#define NODES 7
#define CH 256
#define HID 128
#define P_TOTAL 65536
#define PTS 256                 // points per stream block
#define NPAIR 128               // u64 point-pairs per block = threads
#define CHUNK_CH 8              // channels per pipeline chunk
#define NCHUNK 32               // 256 / 8
#define NSTAGE 3                // pipeline depth
#define ROW_BYTES (PTS * 4)     // 1024 per channel row
#define CHUNK_BYTES (CHUNK_CH * ROW_BYTES)   // 8192
#define STREAM_BLKS 512
#define GEMM_BLKS 14

// static SMEM layout (pass1)
#define SM_BAR_FULL  0          // 3 x u64
#define SM_BAR_EMPTY 64         // 3 x u64
#define SM_N2        128        // 8 floats
#define SM_WD        1024       // Wd[256][8] ull = 16384
#define SM_BUF       17408      // 3 x 8192 = 24576
#define SM_TOTAL     (SM_BUF + NSTAGE * CHUNK_BYTES)   // 41984 < 48KB

typedef unsigned long long ull;

__device__ float g_nw[2 * NODES * CH];          // new_weight [b, n, c]
__device__ float g_attn[2 * NODES * P_TOTAL];   // attn scratch [b, n, p]

// ---------------------------------------------------------------------------
__device__ __forceinline__ ull fma2(ull a, ull b, ull c) {
    ull d;
    asm("fma.rn.f32x2 %0, %1, %2, %3;" : "=l"(d) : "l"(a), "l"(b), "l"(c));
    return d;
}
__device__ __forceinline__ ull pack2(float x, float y) {
    ull r;
    asm("mov.b64 %0, {%1, %2};" : "=l"(r) : "f"(x), "f"(y));
    return r;
}
__device__ __forceinline__ void unpack2(ull v, float& x, float& y) {
    asm("mov.b64 {%0, %1}, %2;" : "=f"(x), "=f"(y) : "l"(v));
}
__device__ __forceinline__ ull ldg64(const float* p) {
    ull v;
    asm volatile("ld.global.b64 %0, [%1];" : "=l"(v) : "l"(p));
    return v;
}
__device__ __forceinline__ void stcs64(float* p, ull v) {
    asm volatile("st.global.cs.b64 [%0], %1;" :: "l"(p), "l"(v));
}
__device__ __forceinline__ void mbar_init(uint32_t a, uint32_t cnt) {
    asm volatile("mbarrier.init.shared.b64 [%0], %1;" :: "r"(a), "r"(cnt) : "memory");
}
__device__ __forceinline__ void mbar_arrive(uint32_t a) {
    asm volatile("mbarrier.arrive.shared.b64 _, [%0];" :: "r"(a) : "memory");
}
__device__ __forceinline__ void mbar_expect_tx(uint32_t a, uint32_t bytes) {
    asm volatile("mbarrier.arrive.expect_tx.shared.b64 _, [%0], %1;"
                 :: "r"(a), "r"(bytes) : "memory");
}
__device__ __forceinline__ void mbar_wait(uint32_t a, uint32_t phase) {
    asm volatile(
        "{\n\t.reg .pred P;\n\t"
        "W_%=:\n\t"
        "mbarrier.try_wait.parity.shared.b64 P, [%0], %1;\n\t"
        "@P bra.uni D_%=;\n\t"
        "bra.uni W_%=;\n\t"
        "D_%=:\n\t}"
        :: "r"(a), "r"(phase) : "memory");
}
__device__ __forceinline__ void bulk_ld(uint32_t dst, const void* src,
                                        uint32_t bytes, uint32_t mbar) {
    asm volatile(
        "cp.async.bulk.shared::cta.global.mbarrier::complete_tx::bytes "
        "[%0], [%1], %2, [%3];"
        :: "r"(dst), "l"(src), "r"(bytes), "r"(mbar) : "memory");
}

// ---------------------------------------------------------------------------
// Pass 1: bulk-async read pipeline. res (128MB) -> n1 -> softmax -> g_attn.
//   Stream blocks (0..511): 256 points, 128 threads (1 u64 point-pair each),
//   32 chunks of 8 channel rows staged through a 3-deep mbarrier ring.
//   Tail blocks (512..525): new_weight GEMM into g_nw.
// ---------------------------------------------------------------------------
__global__ void __launch_bounds__(128, 4) pass1_kernel(
    const float* __restrict__ inp,     // [1,2,7,128]
    const float* __restrict__ res,     // [2, 256, 65536]
    const float* __restrict__ Wres,    // [256, 7]
    const float* __restrict__ nfh,     // [128,1]
    const float* __restrict__ weight)  // [128, 256]
{
    const int tid = threadIdx.x;
    const int bid = blockIdx.x;

    // ---- tail blocks: new_weight GEMM ----
    if (bid >= STREAM_BLKS) {
        const int bn = bid - STREAM_BLKS;    // 0..13
        for (int c = tid; c < CH; c += 128) {
            float acc = 0.f;
#pragma unroll 16
            for (int h = 0; h < HID; ++h)
                acc += __ldg(inp + bn * HID + h) * weight[h * CH + c];
            g_nw[bn * CH + c] = acc;
        }
        return;
    }

    __shared__ __align__(128) char smem[SM_TOTAL];
    uint32_t sb;
    asm("{ .reg .u64 t; cvta.to.shared.u64 t, %1; cvt.u32.u64 %0, t; }"
        : "=r"(sb) : "l"((void*)smem));

    ull*   Wd    = (ull*)(smem + SM_WD);       // [CH][8] duplicated weights
    float* sh_n2 = (float*)(smem + SM_N2);

    const int b    = bid >> 8;                 // 0..1
    const int tile = bid & 255;                // 0..255 (256 points each)
    const int wid  = tid >> 5;
    const int lane = tid & 31;

    // ---- init barriers (full count=1+tx, empty count=128)
    if (tid == 0) {
#pragma unroll
        for (int s = 0; s < NSTAGE; ++s) {
            mbar_init(sb + SM_BAR_FULL + s * 8, 1);
            mbar_init(sb + SM_BAR_EMPTY + s * 8, 128);
        }
    }
    __syncthreads();

    const float* src_base = res + (size_t)b * CH * P_TOTAL + (size_t)tile * PTS;

    // ---- prologue: issue first NSTAGE chunks (thread 0)
    if (tid == 0) {
#pragma unroll
        for (int k = 0; k < NSTAGE; ++k) {
            uint32_t mb = sb + SM_BAR_FULL + k * 8;
            mbar_expect_tx(mb, CHUNK_BYTES);
            const float* src = src_base + (size_t)(k * CHUNK_CH) * P_TOTAL;
            uint32_t dst = sb + SM_BUF + k * CHUNK_BYTES;
#pragma unroll
            for (int i = 0; i < CHUNK_CH; ++i)
                bulk_ld(dst + i * ROW_BYTES, src + (size_t)i * P_TOTAL,
                        ROW_BYTES, mb);
        }
    }

    // ---- overlapped prologue: weights + n2
    for (int c = tid; c < CH; c += 128) {
#pragma unroll
        for (int n = 0; n < NODES; ++n) {
            float w = Wres[c * NODES + n];
            Wd[c * 8 + n] = pack2(w, w);
        }
        Wd[c * 8 + 7] = 0ull;
    }
    if (wid < 4) {
#pragma unroll
        for (int rep = 0; rep < 2; ++rep) {
            int n = wid + rep * 4;
            if (n < NODES) {
                float s = 0.f;
#pragma unroll
                for (int i = 0; i < 4; ++i) {
                    int h = lane + 32 * i;
                    s += __ldg(inp + b * NODES * HID + n * HID + h) * __ldg(nfh + h);
                }
#pragma unroll
                for (int o = 16; o; o >>= 1)
                    s += __shfl_xor_sync(0xffffffffu, s, o);
                if (lane == 0) sh_n2[n] = s;
            }
        }
    }
    __syncthreads();

    float n2s[NODES];
#pragma unroll
    for (int n = 0; n < NODES; ++n) n2s[n] = sh_n2[n];

    ull acc[NODES];
#pragma unroll
    for (int n = 0; n < NODES; ++n) acc[n] = 0ull;

    // ---- main pipeline: consume 32 chunks
#pragma unroll 1
    for (int k = 0; k < NCHUNK; ++k) {
        const int s  = k % NSTAGE;
        const int ph = (k / NSTAGE) & 1;
        mbar_wait(sb + SM_BAR_FULL + s * 8, ph);

        const ull* rows = (const ull*)(smem + SM_BUF + s * CHUNK_BYTES);
#pragma unroll
        for (int i = 0; i < CHUNK_CH; ++i) {
            ull v = rows[i * NPAIR + tid];          // LDS.64, conflict-free
            const int c = k * CHUNK_CH + i;
            const ulonglong2* wr = (const ulonglong2*)(Wd + c * 8);
            ulonglong2 w01 = wr[0];
            ulonglong2 w23 = wr[1];
            ulonglong2 w45 = wr[2];
            ulonglong2 w6p = wr[3];
            acc[0] = fma2(v, w01.x, acc[0]);
            acc[1] = fma2(v, w01.y, acc[1]);
            acc[2] = fma2(v, w23.x, acc[2]);
            acc[3] = fma2(v, w23.y, acc[3]);
            acc[4] = fma2(v, w45.x, acc[4]);
            acc[5] = fma2(v, w45.y, acc[5]);
            acc[6] = fma2(v, w6p.x, acc[6]);
        }
        mbar_arrive(sb + SM_BAR_EMPTY + s * 8);

        // refill this stage with chunk k+NSTAGE
        if (tid == 0 && k + NSTAGE < NCHUNK) {
            const int kn = k + NSTAGE;
            const int ep = 1 ^ ((kn / NSTAGE) & 1);
            mbar_wait(sb + SM_BAR_EMPTY + s * 8, ep);
            uint32_t mb = sb + SM_BAR_FULL + s * 8;
            mbar_expect_tx(mb, CHUNK_BYTES);
            const float* src = src_base + (size_t)(kn * CHUNK_CH) * P_TOTAL;
            uint32_t dst = sb + SM_BUF + s * CHUNK_BYTES;
#pragma unroll
            for (int i = 0; i < CHUNK_CH; ++i)
                bulk_ld(dst + i * ROW_BYTES, src + (size_t)i * P_TOTAL,
                        ROW_BYTES, mb);
        }
    }

    // ---- softmax (2 points) + attn store
    float s0[NODES], s1[NODES];
#pragma unroll
    for (int n = 0; n < NODES; ++n) {
        float x, y;
        unpack2(acc[n], x, y);
        s0[n] = x + n2s[n];
        s1[n] = y + n2s[n];
    }
    float m0 = s0[0], m1 = s1[0];
#pragma unroll
    for (int n = 1; n < NODES; ++n) { m0 = fmaxf(m0, s0[n]); m1 = fmaxf(m1, s1[n]); }
    float t0 = 0.f, t1 = 0.f;
    float e0[NODES], e1[NODES];
#pragma unroll
    for (int n = 0; n < NODES; ++n) {
        e0[n] = __expf(s0[n] - m0); t0 += e0[n];
        e1[n] = __expf(s1[n] - m1); t1 += e1[n];
    }
    float i0 = __fdividef(1.f, t0);
    float i1 = __fdividef(1.f, t1);

    const int pbase = tile * PTS;
#pragma unroll
    for (int n = 0; n < NODES; ++n)
        stcs64(&g_attn[(b * NODES + n) * P_TOTAL + pbase + 2 * tid],
               pack2(e0[n] * i0, e1[n] * i1));
}

// ---------------------------------------------------------------------------
// Pass 2: PURE WRITE stream (R8, unchanged). g_attn (L2) + g_nw -> out.
// ---------------------------------------------------------------------------
__global__ void __launch_bounds__(256, 6) pass2_kernel(
    float* __restrict__ out)           // [2, 256, 65536]
{
    __shared__ ull NW[CH][8];

    const int tid  = threadIdx.x;
    const int b    = blockIdx.x >> 7;
    const int tile = blockIdx.x & 127;

    {
        const int c = tid;
#pragma unroll
        for (int n = 0; n < NODES; ++n) {
            float q = g_nw[(b * NODES + n) * CH + c];
            NW[c][n] = pack2(q, q);
        }
        NW[c][7] = 0ull;
    }
    __syncthreads();

    const int p0 = tile * 512 + 2 * tid;

    ull at[NODES];
#pragma unroll
    for (int n = 0; n < NODES; ++n)
        at[n] = ldg64(&g_attn[(b * NODES + n) * P_TOTAL + p0]);

    float* op = out + (size_t)b * CH * P_TOTAL + p0;
#pragma unroll 4
    for (int c = 0; c < CH; ++c) {
        const ulonglong2* nr = (const ulonglong2*)(&NW[c][0]);
        ulonglong2 q01 = nr[0];
        ulonglong2 q23 = nr[1];
        ulonglong2 q45 = nr[2];
        ulonglong2 q6p = nr[3];
        ull o = 0ull;
        o = fma2(at[0], q01.x, o);
        o = fma2(at[1], q01.y, o);
        o = fma2(at[2], q23.x, o);
        o = fma2(at[3], q23.y, o);
        o = fma2(at[4], q45.x, o);
        o = fma2(at[5], q45.y, o);
        o = fma2(at[6], q6p.x, o);
        float v0, v1;
        unpack2(o, v0, v1);
        stcs64(op + (size_t)c * P_TOTAL, pack2(fmaxf(v0, 0.f), fmaxf(v1, 0.f)));
    }
}

// ---------------------------------------------------------------------------
extern "C" void kernel_launch(void* const* d_in, const int* in_sizes, int n_in,
                              void* d_out, int out_size) {
    const float* inp    = (const float*)d_in[0];  // [1,2,7,128]
    const float* res    = (const float*)d_in[1];  // [2,256,16,64,64]
    const float* Wres   = (const float*)d_in[2];  // [256,7]
    const float* nfh    = (const float*)d_in[3];  // [128,1]
    const float* weight = (const float*)d_in[4];  // [128,256]

    pass1_kernel<<<STREAM_BLKS + GEMM_BLKS, 128>>>(inp, res, Wres, nfh, weight);
    pass2_kernel<<<256, 256>>>((float*)d_out);
}